// round 2
// baseline (speedup 1.0000x reference)
#include <cuda_runtime.h>

// Problem constants: x is [B=8, S=4096, D=1024] fp32; out = x + PE[s, d].
#define PE_S 4096
#define PE_D 1024
#define PE_B 8
#define FLOAT4_PER_BATCH (PE_S * PE_D / 4)   // 1,048,576

// 512 distinct frequencies: power[k] = 10000^(2k/1024), k = j_even/2.
__device__ float g_power[PE_D / 2];

// One-block init kernel: computes powers in double precision, rounds to fp32.
// Runs every launch (graph-capturable, deterministic, ~microsecond).
__global__ void init_power_kernel() {
    int k = threadIdx.x;                       // 0..511
    if (k < PE_D / 2) {
        double j_even = 2.0 * (double)k;
        // 10000^(j/1024) = exp((j/1024) * ln(10000))
        g_power[k] = (float)exp((j_even / 1024.0) * 9.210340371976184);
    }
}

// Accurate sincos: reduce the fp32 angle mod 2pi in double, then sin/cos on
// the small remainder (safe even under --use_fast_math MUFU approximations).
__device__ __forceinline__ void acc_sincos(float angle, float& s_out, float& c_out) {
    double a = (double)angle;
    double k = rint(a * 0.15915494309189535);          // 1/(2*pi)
    float r = (float)(a - k * 6.283185307179586);      // |r| <= pi
    s_out = sinf(r);
    c_out = cosf(r);
}

// Main streaming kernel.
// Thread tid covers (s = tid>>8, d4 = (tid&255)*4): computes one float4 of
// PE once, then streams 8 batches of load-add-store (float4 coalesced).
// Loads are explicitly front-batched (MLP=8) before any store issues.
__global__ void __launch_bounds__(256)
pe_add_kernel(const float4* __restrict__ x, float4* __restrict__ out) {
    int tid = blockIdx.x * 256 + threadIdx.x;      // 0 .. 1,048,575
    int s = tid >> 8;                              // sequence position
    int c = tid & 255;                             // which float4 within the row

    // Columns d4..d4+3 use frequency pairs (j_even = 4c) and (j_even = 4c+2)
    float p0 = g_power[2 * c];
    float p1 = g_power[2 * c + 1];

    float fs = (float)s;
    float a0 = fs / p0;     // matches reference: pos / power, fp32 divide
    float a1 = fs / p1;

    float4 pe;
    acc_sincos(a0, pe.x, pe.y);   // even col -> sin, odd col -> cos
    acc_sincos(a1, pe.z, pe.w);

    // Front-batch all 8 loads (MLP=8 per thread) ...
    float4 v[PE_B];
#pragma unroll
    for (int b = 0; b < PE_B; b++) {
        v[b] = x[(size_t)b * FLOAT4_PER_BATCH + tid];
    }
    // ... then add + store.
#pragma unroll
    for (int b = 0; b < PE_B; b++) {
        float4 o;
        o.x = v[b].x + pe.x;
        o.y = v[b].y + pe.y;
        o.z = v[b].z + pe.z;
        o.w = v[b].w + pe.w;
        out[(size_t)b * FLOAT4_PER_BATCH + tid] = o;
    }
}

extern "C" void kernel_launch(void* const* d_in, const int* in_sizes, int n_in,
                              void* d_out, int out_size) {
    (void)in_sizes; (void)n_in; (void)out_size;
    const float4* x = (const float4*)d_in[0];
    float4* out = (float4*)d_out;

    init_power_kernel<<<1, 512>>>();
    pe_add_kernel<<<FLOAT4_PER_BATCH / 256, 256>>>(x, out);
}

// round 3
// speedup vs baseline: 1.0198x; 1.0198x over previous
#include <cuda_runtime.h>

// x is [B=8, S=4096, D=1024] fp32; out[b,s,d] = x[b,s,d] + PE[s,d].
// PE[s,d] = sin(s / 10000^(j/1024)) for even d (j=d), cos(...) for odd d (j=d-1).
#define PE_S 4096
#define PE_D 1024
#define PE_B 8
#define FLOAT4_PER_BATCH (PE_S * PE_D / 4)   // 1,048,576

// Accurate sincos: reduce the fp32 angle mod 2pi in double, then sin/cos on
// the small remainder (safe even under --use_fast_math MUFU approximations).
// DP cost is ~12 ops/thread, fully hidden under the memory stream (fma pipe
// measured at 7.8% in R2).
__device__ __forceinline__ void acc_sincos(float angle, float& s_out, float& c_out) {
    double a = (double)angle;
    double k = rint(a * 0.15915494309189535);          // 1/(2*pi)
    float r = (float)(a - k * 6.283185307179586);      // |r| <= pi
    s_out = sinf(r);
    c_out = cosf(r);
}

// Single fused kernel. Thread tid covers (s = tid>>8, c = tid&255), i.e. one
// float4 of columns [4c .. 4c+3]. It computes the PE float4 once (2x exp2f +
// 2x accurate sincos) and streams 8 batches of load-add-store, loads
// front-batched (MLP=8) ahead of the stores.
__global__ void __launch_bounds__(256)
pe_add_kernel(const float4* __restrict__ x, float4* __restrict__ out) {
    int tid = blockIdx.x * 256 + threadIdx.x;      // 0 .. 1,048,575
    int s = tid >> 8;                              // sequence position
    int c = tid & 255;                             // float4 index within the row

    // power for column pair 0: 10000^(4c/1024)   = 2^(c * log2(1e4)/256)
    // power for column pair 1: 10000^((4c+2)/1024) = 2^(c * log2(1e4)/256 + log2(1e4)/512)
    const float K = 0.051905126482615075f;         // log2(10000)/256
    const float C = 0.025952563241307537f;         // log2(10000)/512
    float fc = (float)c;
    float p0 = exp2f(fc * K);
    float p1 = exp2f(fmaf(fc, K, C));

    float fs = (float)s;
    float a0 = fs / p0;     // matches reference form: pos / power, fp32 divide
    float a1 = fs / p1;

    float4 pe;
    acc_sincos(a0, pe.x, pe.y);   // even col -> sin, odd col -> cos
    acc_sincos(a1, pe.z, pe.w);

    // Front-batch all 8 loads (streaming, evict-first: zero reuse, 256MB
    // footprint vs 126MB L2) ...
    float4 v[PE_B];
#pragma unroll
    for (int b = 0; b < PE_B; b++) {
        v[b] = __ldcs(&x[(size_t)b * FLOAT4_PER_BATCH + tid]);
    }
    // ... then add + streaming store.
#pragma unroll
    for (int b = 0; b < PE_B; b++) {
        float4 o;
        o.x = v[b].x + pe.x;
        o.y = v[b].y + pe.y;
        o.z = v[b].z + pe.z;
        o.w = v[b].w + pe.w;
        __stcs(&out[(size_t)b * FLOAT4_PER_BATCH + tid], o);
    }
}

extern "C" void kernel_launch(void* const* d_in, const int* in_sizes, int n_in,
                              void* d_out, int out_size) {
    (void)in_sizes; (void)n_in; (void)out_size;
    const float4* x = (const float4*)d_in[0];
    float4* out = (float4*)d_out;

    pe_add_kernel<<<FLOAT4_PER_BATCH / 256, 256>>>(x, out);
}